// round 8
// baseline (speedup 1.0000x reference)
#include <cuda_runtime.h>
#include <math.h>

#define T_DATA 40000
#define E_E    2000
#define E_I    400
#define SUB    32
#define T_NO   200
#define NB     17

#define HALF_T   20480           // pipeline split point (multiple of 8 and 2048)
#define ACC_A    (HALF_T / 8)    // 2560 accum blocks, first half
#define ACC_B    ((T_DATA - HALF_T + 7) / 8)  // 2440 accum blocks, second half
#define TLEN     2048            // conv tile (256 threads * 8 outputs)
#define NXT      10              // conv x-tiles per half
#define NCONV    (17 * NXT)      // 16 pair planes + hist plane

// Output layout (flattened tuple): V_out[40000], Z_out[40000], out_filters[65*200]
#define ZOFF 40000
#define FOFF 80000

// packed fp32x2 FMA (Blackwell FFMA2 — only reachable via PTX)
#define FMA2(d, a, b, c) \
    asm("fma.rn.f32x2 %0, %1, %2, %3;" : "=l"(d) : "l"(a), "l"(b), "l"(c))

#define PH(i) ((i) + ((i) >> 3))
typedef unsigned long long ull;

// -------- device scratch (allocation-free rule: __device__ globals) --------
__device__ float g_eT[SUB * T_DATA];     // e counts, [s][t]
__device__ float g_iT[SUB * T_DATA];     // i counts, [s][t]
__device__ float g_u[SUB * T_DATA];      // fused input e + c_s*i, [s][t]
__device__ float g_syn[T_DATA * SUB];    // conv output, [t][s]
__device__ float g_hf[T_DATA];           // history filter of observed Z
__device__ int   g_subE[E_E];
__device__ int   g_subI[E_I];
__device__ float g_ekern[SUB * T_NO];
__device__ float g_ikern[SUB * T_NO];
__device__ float g_hist[T_NO];
__device__ float g_okern[T_NO];
__device__ float g_A[SUB * SUB];         // C_den * exp(W_sub)
__device__ float g_c[SUB];
__device__ int   g_fused;
__device__ int   g_Js[SUB];
__device__ int   g_J[16];
__device__ float g_zout[T_DATA];

// =====================================================================
// K0: prep — filters, basis, A matrix, column->subunit ids, filter block
// =====================================================================
__global__ void prep_kernel(const float* __restrict__ C_den,
                            const float* __restrict__ C_syn_e,
                            const float* __restrict__ C_syn_i,
                            const float* __restrict__ Tau_syn,
                            const float* __restrict__ Delta_syn,
                            const float* __restrict__ W_syn,
                            const float* __restrict__ W_sub,
                            const float* __restrict__ W_hist,
                            const float* __restrict__ Tau_out,
                            const float* __restrict__ W_out,
                            float* __restrict__ d_out)
{
    int tid  = threadIdx.x;
    int gtid = blockIdx.x * blockDim.x + tid;
    int gsz  = gridDim.x * blockDim.x;

    for (int e = gtid; e < E_E; e += gsz) {
        int s = 0;
        #pragma unroll
        for (int k = 0; k < SUB; k++)
            if (C_syn_e[k * E_E + e] != 0.f) s = k;
        g_subE[e] = s;
    }
    for (int e = gtid; e < E_I; e += gsz) {
        int s = 0;
        #pragma unroll
        for (int k = 0; k < SUB; k++)
            if (C_syn_i[k * E_I + e] != 0.f) s = k;
        g_subI[e] = s;
    }

    if (blockIdx.x == 0) {
        for (int i = tid; i < SUB * T_NO; i += blockDim.x) {
            int s = i / T_NO, tt = i % T_NO;
            float te  = fmaxf((float)tt - expf(Delta_syn[s * 2 + 0]), 0.f);
            float tte = te / expf(Tau_syn[s * 2 + 0]);
            float ek  = tte * expf(-tte) * expf(W_syn[s * 2 + 0]);
            float ti  = fmaxf((float)tt - expf(Delta_syn[s * 2 + 1]), 0.f);
            float tti = ti / expf(Tau_syn[s * 2 + 1]);
            float ik  = -tti * expf(-tti) * expf(W_syn[s * 2 + 1]);
            g_ekern[i] = ek;
            g_ikern[i] = ik;
            d_out[FOFF + s * T_NO + tt]         = ek;
            d_out[FOFF + (SUB + s) * T_NO + tt] = ik;
        }
    }
    if (blockIdx.x == 1) {
        const float PI  = 3.14159274101f;
        const float PI2 = 1.57079637051f;
        for (int tt = tid; tt < T_NO; tt += blockDim.x) {
            float raw = 4.0f * logf((float)tt + 1.0f);
            float h = 0.f;
            #pragma unroll
            for (int n = 0; n < NB; n++) {
                float phi = PI2 * (float)n;
                float d = raw - phi;
                float b = (raw >= phi - PI && raw <= phi + PI) ? (0.5f * cosf(d) + 0.5f) : 0.f;
                h += expf(W_hist[n]) * b;
            }
            h = -h;
            g_hist[tt] = h;
            d_out[FOFF + 64 * T_NO + tt] = h;

            float tto = (float)tt / expf(Tau_out[0]);
            g_okern[tt] = tto * expf(-tto) * expf(W_out[0]);
        }
    }
    if (blockIdx.x == 2) {
        for (int i = tid; i < SUB * SUB; i += blockDim.x)
            g_A[i] = C_den[i] * expf(W_sub[i & 31]);
    }
}

// =====================================================================
// K0b: fusibility check + truncated tap supports
// =====================================================================
__global__ void prep2_kernel()
{
    __shared__ int okArr[SUB];
    __shared__ int JsArr[SUB];
    int s = threadIdx.x;
    if (s < SUB) {
        float best = 0.f; int jm = 0;
        for (int j = 0; j < T_NO; j++) {
            float a = fabsf(g_ekern[s * T_NO + j]);
            if (a > best) { best = a; jm = j; }
        }
        float c = (best > 0.f) ? g_ikern[s * T_NO + jm] / g_ekern[s * T_NO + jm] : 0.f;
        float maxerr = 0.f, maxi = 0.f;
        float totE = 0.f, totI = 0.f;
        for (int j = 0; j < T_NO; j++) {
            float ek = g_ekern[s * T_NO + j];
            float ik = g_ikern[s * T_NO + j];
            maxerr = fmaxf(maxerr, fabsf(ik - c * ek));
            maxi   = fmaxf(maxi, fabsf(ik));
            totE  += fabsf(ek);
            totI  += fabsf(ik);
        }
        okArr[s] = (best > 0.f) && (maxerr <= 1e-5f * (maxi + 1e-20f));
        g_c[s] = c;

        float tailE = 0.f, tailI = 0.f;
        int J = T_NO;
        for (int j = T_NO - 1; j >= 8; j--) {
            tailE += fabsf(g_ekern[s * T_NO + j]);
            tailI += fabsf(g_ikern[s * T_NO + j]);
            if (tailE <= 1e-7f * totE && tailI <= 1e-7f * totI) J = j;
        }
        J = (J + 7) & ~7;
        if (J > T_NO) J = T_NO;
        JsArr[s] = J;
        g_Js[s] = J;
    }
    __syncthreads();
    if (threadIdx.x == 0) {
        int all = 1;
        for (int k = 0; k < SUB; k++) all &= okArr[k];
        g_fused = all;
        for (int y = 0; y < 16; y++) {
            int J = JsArr[2 * y] > JsArr[2 * y + 1] ? JsArr[2 * y] : JsArr[2 * y + 1];
            g_J[y] = J;
        }
    }
}

// =====================================================================
// accum role: one warp per timestep, 8 warps/block (tBlock = block's t/8)
// =====================================================================
__device__ __forceinline__ void accum_body(const float* __restrict__ S_e,
                                           const float* __restrict__ S_i,
                                           int tBlock)
{
    __shared__ float accE[8][33];
    __shared__ float accI[8][33];
    __shared__ char  ssubE[E_E];
    __shared__ char  ssubI[E_I];
    __shared__ float sc[SUB];

    int tid  = threadIdx.x;
    int warp = tid >> 5;
    int lane = tid & 31;
    int t = tBlock * 8 + warp;

    for (int i = tid; i < E_E; i += 256) ssubE[i] = (char)g_subE[i];
    for (int i = tid; i < E_I; i += 256) ssubI[i] = (char)g_subI[i];
    if (tid < SUB) sc[tid] = g_c[tid];
    accE[warp][lane] = 0.f;
    accI[warp][lane] = 0.f;
    __syncthreads();

    const float4 z4 = make_float4(0.f, 0.f, 0.f, 0.f);

    {
        const float4* rowE = (const float4*)(S_e + (size_t)t * E_E);
        float4 v[8];
        #pragma unroll 1
        for (int it0 = 0; it0 < 16; it0 += 8) {
            #pragma unroll
            for (int u = 0; u < 8; u++) {
                int k = (it0 + u) * 32 + lane;
                v[u] = (k < 500) ? __ldcs(rowE + k) : z4;
            }
            #pragma unroll
            for (int u = 0; u < 8; u++) {
                int e = ((it0 + u) * 32 + lane) * 4;
                if (v[u].x != 0.f) atomicAdd(&accE[warp][(int)ssubE[e + 0]], v[u].x);
                if (v[u].y != 0.f) atomicAdd(&accE[warp][(int)ssubE[e + 1]], v[u].y);
                if (v[u].z != 0.f) atomicAdd(&accE[warp][(int)ssubE[e + 2]], v[u].z);
                if (v[u].w != 0.f) atomicAdd(&accE[warp][(int)ssubE[e + 3]], v[u].w);
            }
        }
    }
    {
        const float4* rowI = (const float4*)(S_i + (size_t)t * E_I);
        float4 v[4];
        #pragma unroll
        for (int u = 0; u < 4; u++) {
            int k = u * 32 + lane;
            v[u] = (k < 100) ? __ldcs(rowI + k) : z4;
        }
        #pragma unroll
        for (int u = 0; u < 4; u++) {
            int e = (u * 32 + lane) * 4;
            if (v[u].x != 0.f) atomicAdd(&accI[warp][(int)ssubI[e + 0]], v[u].x);
            if (v[u].y != 0.f) atomicAdd(&accI[warp][(int)ssubI[e + 1]], v[u].y);
            if (v[u].z != 0.f) atomicAdd(&accI[warp][(int)ssubI[e + 2]], v[u].z);
            if (v[u].w != 0.f) atomicAdd(&accI[warp][(int)ssubI[e + 3]], v[u].w);
        }
    }
    __syncthreads();

    int s  = tid >> 3;
    int tt = tid & 7;
    int tg = tBlock * 8 + tt;
    float e = accE[tt][s];
    float i = accI[tt][s];
    g_eT[s * T_DATA + tg] = e;
    g_iT[s * T_DATA + tg] = i;
    g_u [s * T_DATA + tg] = fmaf(sc[s], i, e);
}

// =====================================================================
// conv role: plane y (0..15 fused subunit pairs, 16 = hist), tile tBase,
// 256 threads x 8 outputs (TLEN=2048). FFMA2, truncated taps.
// =====================================================================
__device__ __forceinline__ void conv_body(const float* __restrict__ Z,
                                          int y, int tBase)
{
    __shared__ float2 xei[2532];
    __shared__ float2 kei[T_NO];

    int tid = threadIdx.x;

    if (y < 16) {
        int fused = g_fused;
        int npass = fused ? 1 : 2;

        #pragma unroll 1
        for (int p = 0; p < npass; p++) {
            if (p) __syncthreads();

            int J;
            if (fused) {
                int s0 = 2 * y, s1 = s0 + 1;
                J = g_J[y];
                for (int L = tid; L < TLEN + 200; L += 256) {
                    int t = tBase + L - 200;
                    bool ok = (t >= 0) && (t < T_DATA);
                    float u0 = ok ? g_u[s0 * T_DATA + t] : 0.f;
                    float u1 = ok ? g_u[s1 * T_DATA + t] : 0.f;
                    xei[PH(L)] = make_float2(u0, u1);
                }
                for (int j = tid; j < T_NO; j += 256)
                    kei[j] = make_float2(g_ekern[s0 * T_NO + j], g_ekern[s1 * T_NO + j]);
            } else {
                int s = 2 * y + p;
                J = g_Js[s];
                for (int L = tid; L < TLEN + 200; L += 256) {
                    int t = tBase + L - 200;
                    bool ok = (t >= 0) && (t < T_DATA);
                    float e = ok ? g_eT[s * T_DATA + t] : 0.f;
                    float i = ok ? g_iT[s * T_DATA + t] : 0.f;
                    xei[PH(L)] = make_float2(e, i);
                }
                for (int j = tid; j < T_NO; j += 256)
                    kei[j] = make_float2(g_ekern[s * T_NO + j], g_ikern[s * T_NO + j]);
            }
            __syncthreads();

            const ull* xp = (const ull*)xei;
            const ull* kp = (const ull*)kei;

            ull acc2[8];
            #pragma unroll
            for (int r = 0; r < 8; r++) acc2[r] = 0ull;

            ull w2[15];
            int b = tid * 8 + 192;
            #pragma unroll
            for (int c = 0; c < 15; c++) w2[c] = xp[PH(b + c)];

            ull kk2[8];
            #pragma unroll 1
            for (int j0 = 0; j0 < J; j0 += 8) {
                #pragma unroll
                for (int jj = 0; jj < 8; jj++) kk2[jj] = kp[j0 + jj];
                #pragma unroll
                for (int jj = 0; jj < 8; jj++) {
                    #pragma unroll
                    for (int r = 0; r < 8; r++)
                        FMA2(acc2[r], kk2[jj], w2[r + 7 - jj], acc2[r]);
                }
                if (j0 + 8 < J) {
                    b -= 8;
                    #pragma unroll
                    for (int c = 14; c >= 8; c--) w2[c] = w2[c - 8];
                    #pragma unroll
                    for (int c = 0; c < 8; c++) w2[c] = xp[PH(b + c)];
                }
            }

            #pragma unroll
            for (int r = 0; r < 8; r++) {
                int t = tBase + tid * 8 + r;
                if (t < T_DATA) {
                    float lo, hi;
                    asm("mov.b64 {%0,%1}, %2;" : "=f"(lo), "=f"(hi) : "l"(acc2[r]));
                    if (fused) {
                        g_syn[t * SUB + 2 * y]     = lo;
                        g_syn[t * SUB + 2 * y + 1] = hi;
                    } else {
                        g_syn[t * SUB + 2 * y + p] = lo + hi;
                    }
                }
            }
        }
    } else {
        // ---- history-conv plane: hf[t] = sum_j hist[j] * Z[t-1-j] ----
        float* zs = (float*)xei;
        float* sh = (float*)kei;
        for (int L = tid; L < TLEN + 200; L += 256) {
            int t = tBase + L - 200;
            zs[PH(L)] = (t >= 0 && t < T_DATA) ? Z[t] : 0.f;
        }
        for (int j = tid; j < T_NO; j += 256) sh[j] = g_hist[j];
        __syncthreads();

        float acc[8];
        #pragma unroll
        for (int r = 0; r < 8; r++) acc[r] = 0.f;

        float w[15];
        int b = tid * 8 + 192;
        #pragma unroll
        for (int c = 0; c < 15; c++) w[c] = zs[PH(b + c)];

        float kk[8];
        #pragma unroll 1
        for (int j0 = 0; j0 < 200; j0 += 8) {
            #pragma unroll
            for (int jj = 0; jj < 8; jj++) kk[jj] = sh[j0 + jj];
            #pragma unroll
            for (int jj = 0; jj < 8; jj++) {
                #pragma unroll
                for (int r = 0; r < 8; r++)
                    acc[r] = fmaf(kk[jj], w[r + 7 - jj], acc[r]);
            }
            if (j0 + 8 < 200) {
                b -= 8;
                #pragma unroll
                for (int c = 14; c >= 8; c--) w[c] = w[c - 8];
                #pragma unroll
                for (int c = 0; c < 8; c++) w[c] = zs[PH(b + c)];
            }
        }
        #pragma unroll
        for (int r = 0; r < 8; r++) {
            int t = tBase + tid * 8 + r;
            if (t < T_DATA) g_hf[t] = acc[r];
        }
    }
}

// =====================================================================
// K1: accum over first half [0, HALF_T)
// =====================================================================
__global__ void __launch_bounds__(256) accumA_kernel(const float* __restrict__ S_e,
                                                     const float* __restrict__ S_i)
{
    accum_body(S_e, S_i, blockIdx.x);
}

// =====================================================================
// K2 (mixed): blocks [0, NCONV) = conv of first half (+hist plane),
// blocks [NCONV, NCONV+ACC_B) = accum of second half. The conv blocks
// only read accumA output (t < HALF_T), so they overlap accumB freely.
// =====================================================================
__global__ void __launch_bounds__(256) mixed_kernel(const float* __restrict__ S_e,
                                                    const float* __restrict__ S_i,
                                                    const float* __restrict__ Z)
{
    int bx = blockIdx.x;
    if (bx < NCONV) {
        int y  = bx / NXT;
        int xt = bx % NXT;
        conv_body(Z, y, xt * TLEN);
    } else {
        accum_body(S_e, S_i, HALF_T / 8 + (bx - NCONV));
    }
}

// =====================================================================
// K3: conv of second half [HALF_T, T_DATA)
// =====================================================================
__global__ void __launch_bounds__(256) convB_kernel(const float* __restrict__ Z)
{
    int y  = blockIdx.x / NXT;
    int xt = blockIdx.x % NXT;
    conv_body(Z, y, HALF_T + xt * TLEN);
}

// =====================================================================
// K4: per-timestep tree walk, 2 timesteps/thread (ILP over tanh chain)
// =====================================================================
__global__ void __launch_bounds__(256) tree_kernel(const float* __restrict__ Theta,
                                                   float* __restrict__ d_out)
{
    __shared__ float sA[SUB * SUB];
    __shared__ float sTheta[SUB];

    int tid = threadIdx.x;
    int t0 = blockIdx.x * 256 + tid;

    for (int i = tid; i < SUB * SUB; i += 256) sA[i] = g_A[i];
    if (tid < SUB) sTheta[tid] = Theta[tid];
    __syncthreads();
    if (t0 >= T_DATA / 2) return;
    int t1 = t0 + T_DATA / 2;

    float syn0[SUB], syn1[SUB];
    const float4* sr0 = (const float4*)(g_syn + (size_t)t0 * SUB);
    const float4* sr1 = (const float4*)(g_syn + (size_t)t1 * SUB);
    #pragma unroll
    for (int i = 0; i < 8; i++) {
        float4 a = sr0[i];
        syn0[4*i+0] = a.x; syn0[4*i+1] = a.y; syn0[4*i+2] = a.z; syn0[4*i+3] = a.w;
        float4 b = sr1[i];
        syn1[4*i+0] = b.x; syn1[4*i+1] = b.y; syn1[4*i+2] = b.z; syn1[4*i+3] = b.w;
    }

    float sub0[SUB], sub1[SUB];
    #pragma unroll
    for (int i = 0; i < SUB; i++) { sub0[i] = 0.f; sub1[i] = 0.f; }

    #pragma unroll
    for (int idx = SUB - 1; idx >= 1; --idx) {
        float th = sTheta[idx];
        float c0 = syn0[idx] + th;
        float c1 = syn1[idx] + th;
        if (2 * idx + 1 < SUB) {
            float a = sA[idx * SUB + 2 * idx + 1];
            c0 = fmaf(a, sub0[2 * idx + 1], c0);
            c1 = fmaf(a, sub1[2 * idx + 1], c1);
        }
        if (2 * idx + 2 < SUB) {
            float a = sA[idx * SUB + 2 * idx + 2];
            c0 = fmaf(a, sub0[2 * idx + 2], c0);
            c1 = fmaf(a, sub1[2 * idx + 2], c1);
        }
        sub0[idx] = tanhf(c0);
        sub1[idx] = tanhf(c1);
    }

    float r0 = g_hf[t0] + syn0[0] + sTheta[0];
    float r1 = g_hf[t1] + syn1[0] + sTheta[0];
    r0 = fmaf(sA[1], sub0[1], r0); r0 = fmaf(sA[2], sub0[2], r0);
    r1 = fmaf(sA[1], sub1[1], r1); r1 = fmaf(sA[2], sub1[2], r1);

    float z0 = (r0 > 0.f) ? 1.f : 0.f;
    float z1 = (r1 > 0.f) ? 1.f : 0.f;
    d_out[ZOFF + t0] = z0;  g_zout[t0] = z0;
    d_out[ZOFF + t1] = z1;  g_zout[t1] = z1;
}

// =====================================================================
// K5: output alpha-kernel conv of the spike train Z_out -> V_out
// =====================================================================
__global__ void __launch_bounds__(256) vout_kernel(float* __restrict__ d_out)
{
    __shared__ float ok[T_NO];
    __shared__ float zw[456];

    int tid = threadIdx.x;
    int tBase = blockIdx.x * 256;
    int t = tBase + tid;

    for (int i = tid; i < T_NO; i += 256) ok[i] = g_okern[i];
    for (int i = tid; i < 456; i += 256) {
        int tz = tBase - 200 + i;
        zw[i] = (tz >= 0 && tz < T_DATA) ? g_zout[tz] : 0.f;
    }
    __syncthreads();
    if (t >= T_DATA) return;

    float v = 0.f;
    #pragma unroll 4
    for (int j = 0; j < T_NO; j++) v = fmaf(ok[j], zw[tid + 199 - j], v);
    d_out[t] = v;
}

// =====================================================================
extern "C" void kernel_launch(void* const* d_in, const int* in_sizes, int n_in,
                              void* d_out, int out_size)
{
    const float* S_e      = (const float*)d_in[0];
    const float* S_i      = (const float*)d_in[1];
    const float* Z        = (const float*)d_in[2];
    const float* C_den    = (const float*)d_in[3];
    const float* C_syn_e  = (const float*)d_in[4];
    const float* C_syn_i  = (const float*)d_in[5];
    const float* Tau_syn  = (const float*)d_in[6];
    const float* Delta_syn= (const float*)d_in[7];
    const float* W_syn    = (const float*)d_in[8];
    const float* W_sub    = (const float*)d_in[9];
    const float* W_hist   = (const float*)d_in[10];
    const float* Theta    = (const float*)d_in[11];
    const float* Tau_out  = (const float*)d_in[12];
    const float* W_out    = (const float*)d_in[13];
    float* out = (float*)d_out;

    prep_kernel<<<64, 256>>>(C_den, C_syn_e, C_syn_i, Tau_syn, Delta_syn,
                             W_syn, W_sub, W_hist, Tau_out, W_out, out);

    prep2_kernel<<<1, 32>>>();

    accumA_kernel<<<ACC_A, 256>>>(S_e, S_i);

    mixed_kernel<<<NCONV + ACC_B, 256>>>(S_e, S_i, Z);

    convB_kernel<<<NCONV, 256>>>(Z);

    tree_kernel<<<(T_DATA / 2 + 255) / 256, 256>>>(Theta, out);

    vout_kernel<<<(T_DATA + 255) / 256, 256>>>(out);
}